// round 13
// baseline (speedup 1.0000x reference)
#include <cuda_runtime.h>
#include <cuda_fp16.h>
#include <cstddef>

// Problem constants (dataset: B=2, N=50000, D=16)
#define MAXB 2
#define MAXN 50000

// 16B gather record per point: [h2(p1.x,p1.y), h2(p1.z,disp.x),
// h2(disp.y,disp.z), pad]. ONE LDG.128 per neighbor gather (was two).
// disp = xyz2-xyz1 (~0.1 scale) keeps full f16 relative precision, and the
// dominant f16 error lands in the symmetric part of S (rotation-invisible).
__device__ uint4 g_rec[MAXB * MAXN];

// FMA-pipe inverse sqrt (no MUFU). 2 Newton steps: rel err ~5e-6.
__device__ __forceinline__ float frsqrt_fast(float x) {
    float xh = 0.5f * x;
    float y = __int_as_float(0x5f3759df - (__float_as_int(x) >> 1));
    y = y * (1.5f - xh * y * y);
    y = y * (1.5f - xh * y * y);
    return y;
}

__device__ __forceinline__ unsigned pack_h2(float a, float b) {
    __half2 h = __floats2half2_rn(a, b);
    return *reinterpret_cast<unsigned*>(&h);
}

__device__ __forceinline__ float2 unpack_h2(unsigned u) {
    __half2 h = *reinterpret_cast<__half2*>(&u);
    return __half22float2(h);
}

// ---------------------------------------------------------------------------
// Kernel 1: build 16B f16 records. Thread t = point t; stride-3 scalar loads
// (coalesced sectors), one 16B store per thread (fully coalesced).
// ---------------------------------------------------------------------------
__global__ void pack_kernel(const float* __restrict__ xyz1,
                            const float* __restrict__ xyz2, int npts) {
    int t = blockIdx.x * blockDim.x + threadIdx.x;
    if (t >= npts) return;
    float ax = xyz1[3 * t + 0], ay = xyz1[3 * t + 1], az = xyz1[3 * t + 2];
    float cx = xyz2[3 * t + 0], cy = xyz2[3 * t + 1], cz = xyz2[3 * t + 2];
    float dx = cx - ax, dy = cy - ay, dz = cz - az;
    uint4 r;
    r.x = pack_h2(ax, ay);
    r.y = pack_h2(az, dx);
    r.z = pack_h2(dy, dz);
    r.w = 0u;
    g_rec[t] = r;
}

// ---------------------------------------------------------------------------
// Exact Givens Jacobi rotation (FMA-pipe only): zeroes K[p][q].
// ---------------------------------------------------------------------------
template <int p, int q>
__device__ __forceinline__ void jrot(float K[3][3], float V[3][3]) {
    constexpr int r3 = 3 - p - q;
    float apq = K[p][q];
    float ad = K[p][p] - K[q][q];
    float b2 = 2.f * apq;
    float rsq = fmaf(ad, ad, b2 * b2) + 1e-30f;
    float w = frsqrt_fast(rsq);
    float r = rsq * w;  // sqrt(rsq)
    float u = r + fabsf(ad);
    float kk = frsqrt_fast(2.f * r * u);
    float c0 = u * kk;
    float s0 = b2 * kk;
    float c, s;
    if (ad >= 0.f) { c = c0; s = s0; }
    else           { c = fabsf(s0); s = copysignf(c0, b2); }

    float kpp = K[p][p], kqq = K[q][q], kpr = K[p][r3], kqr = K[q][r3];
    float cc = c * c, ss = s * s, cs = c * s;
    K[p][p] = cc * kpp + 2.f * cs * apq + ss * kqq;
    K[q][q] = ss * kpp - 2.f * cs * apq + cc * kqq;
    float npq = cs * (kqq - kpp) + (cc - ss) * apq;
    K[p][q] = npq; K[q][p] = npq;
    float npr = fmaf(c, kpr, s * kqr);
    float nqr = fmaf(-s, kpr, c * kqr);
    K[p][r3] = npr; K[r3][p] = npr;
    K[q][r3] = nqr; K[r3][q] = nqr;

#pragma unroll
    for (int i2 = 0; i2 < 3; i2++) {
        float vp = V[i2][p], vq = V[i2][q];
        V[i2][p] = fmaf(c, vp, s * vq);
        V[i2][q] = fmaf(-s, vp, c * vq);
    }
}

// ---------------------------------------------------------------------------
// Kernel 2 (fused): ONE thread per (batch, vertex). 16 neighbor gathers in
// 2 waves of 8 front-batched LDG.128 (one per record). Self point in f32
// straight from xyz1/xyz2 (zero self error; errors land symmetric).
// ---------------------------------------------------------------------------
__global__ __launch_bounds__(256, 3) void arap_fused_kernel(
    const float* __restrict__ xyz1, const float* __restrict__ xyz2,
    const int* __restrict__ nbr, const int* __restrict__ numN,
    const int* __restrict__ accN, const float* __restrict__ wgt,
    float* __restrict__ out, int n) {
    int i = blockIdx.x * blockDim.x + threadIdx.x;
    int b = blockIdx.y;
    if (i >= n) return;
    int vbase = b * n;

    // CSR metadata first so wave-0 index loads overlap the self loads.
    int start = accN[i];
    int cnt = numN[i];

    // Self point, full f32 (coalesced-ish stride-3 loads).
    const float* s1 = xyz1 + 3 * (size_t)(vbase + i);
    const float* s2 = xyz2 + 3 * (size_t)(vbase + i);
    float p1x = s1[0], p1y = s1[1], p1z = s1[2];
    float dix = s2[0] - p1x, diy = s2[1] - p1y, diz = s2[2] - p1z;

    const uint4* __restrict__ rec = g_rec;

    float S00 = 0.f, S01 = 0.f, S02 = 0.f;
    float S10 = 0.f, S11 = 0.f, S12 = 0.f;
    float S20 = 0.f, S21 = 0.f, S22 = 0.f;

    auto accum = [&](uint4 r, float wv) {
        float2 f0 = unpack_h2(r.x);   // p1.x, p1.y
        float2 f1 = unpack_h2(r.y);   // p1.z, disp.x
        float2 f2 = unpack_h2(r.z);   // disp.y, disp.z
        float d1x = p1x - f0.x, d1y = p1y - f0.y, d1z = p1z - f1.x;
        float d2x = d1x + (dix - f1.y);
        float d2y = d1y + (diy - f2.x);
        float d2z = d1z + (diz - f2.y);
        float wx = wv * d1x, wy = wv * d1y, wz = wv * d1z;
        S00 = fmaf(wx, d2x, S00); S01 = fmaf(wx, d2y, S01); S02 = fmaf(wx, d2z, S02);
        S10 = fmaf(wy, d2x, S10); S11 = fmaf(wy, d2y, S11); S12 = fmaf(wy, d2z, S12);
        S20 = fmaf(wz, d2x, S20); S21 = fmaf(wz, d2y, S21); S22 = fmaf(wz, d2z, S22);
    };

    if (cnt == 16 && (start & 3) == 0) {
        const int4* n4 = (const int4*)(nbr + start);
        const float4* w4 = (const float4*)(wgt + start);
#pragma unroll
        for (int wave = 0; wave < 2; wave++) {
            int4 na = n4[2 * wave + 0];
            int4 nb = n4[2 * wave + 1];
            float4 wa = w4[2 * wave + 0];
            float4 wb = w4[2 * wave + 1];
            // Front-batch 8 record gathers (8 LDG.128 = 32 regs in flight).
            uint4 r0 = rec[vbase + na.x];
            uint4 r1 = rec[vbase + na.y];
            uint4 r2 = rec[vbase + na.z];
            uint4 r3 = rec[vbase + na.w];
            uint4 r4 = rec[vbase + nb.x];
            uint4 r5 = rec[vbase + nb.y];
            uint4 r6 = rec[vbase + nb.z];
            uint4 r7 = rec[vbase + nb.w];
            accum(r0, wa.x);
            accum(r1, wa.y);
            accum(r2, wa.z);
            accum(r3, wa.w);
            accum(r4, wb.x);
            accum(r5, wb.y);
            accum(r6, wb.z);
            accum(r7, wb.w);
        }
    } else {
        for (int k = 0; k < cnt; k++) {
            int j = nbr[start + k];
            accum(rec[vbase + j], wgt[start + k]);
        }
    }

    // ---- Procrustes solve ----
    float K[3][3];
    K[0][0] = S00 * S00 + S10 * S10 + S20 * S20;
    K[0][1] = S00 * S01 + S10 * S11 + S20 * S21;
    K[0][2] = S00 * S02 + S10 * S12 + S20 * S22;
    K[1][1] = S01 * S01 + S11 * S11 + S21 * S21;
    K[1][2] = S01 * S02 + S11 * S12 + S21 * S22;
    K[2][2] = S02 * S02 + S12 * S12 + S22 * S22;
    K[1][0] = K[0][1]; K[2][0] = K[0][2]; K[2][1] = K[1][2];

    float V[3][3] = {{1.f, 0.f, 0.f}, {0.f, 1.f, 0.f}, {0.f, 0.f, 1.f}};
#pragma unroll
    for (int sweep = 0; sweep < 4; sweep++) {
        jrot<0, 1>(K, V);
        jrot<1, 2>(K, V);
        jrot<0, 2>(K, V);
    }

    // Sort eigenpairs descending.
    float l0 = K[0][0], l1 = K[1][1], l2 = K[2][2], tt;
    if (l0 < l1) {
        tt = l0; l0 = l1; l1 = tt;
        tt = V[0][0]; V[0][0] = V[0][1]; V[0][1] = tt;
        tt = V[1][0]; V[1][0] = V[1][1]; V[1][1] = tt;
        tt = V[2][0]; V[2][0] = V[2][1]; V[2][1] = tt;
    }
    if (l0 < l2) {
        tt = l0; l0 = l2; l2 = tt;
        tt = V[0][0]; V[0][0] = V[0][2]; V[0][2] = tt;
        tt = V[1][0]; V[1][0] = V[1][2]; V[1][2] = tt;
        tt = V[2][0]; V[2][0] = V[2][2]; V[2][2] = tt;
    }
    if (l1 < l2) {
        tt = l1; l1 = l2; l2 = tt;
        tt = V[0][1]; V[0][1] = V[0][2]; V[0][2] = tt;
        tt = V[1][1]; V[1][1] = V[1][2]; V[1][2] = tt;
        tt = V[2][1]; V[2][1] = V[2][2]; V[2][2] = tt;
    }

    // Force det(V) = +1.
    {
        float cx = V[1][1] * V[2][2] - V[2][1] * V[1][2];
        float cy = V[2][1] * V[0][2] - V[0][1] * V[2][2];
        float cz = V[0][1] * V[1][2] - V[1][1] * V[0][2];
        float det = V[0][0] * cx + V[1][0] * cy + V[2][0] * cz;
        if (det < 0.f) { V[0][2] = -V[0][2]; V[1][2] = -V[1][2]; V[2][2] = -V[2][2]; }
    }

    // u0 = S v0 / |S v0|, u1 = S v1 / |S v1|, u2 = u0 x u1 (det(U)=+1: the
    // reference's reflection fix lands on the smallest singular direction).
    float b0x = S00 * V[0][0] + S01 * V[1][0] + S02 * V[2][0];
    float b0y = S10 * V[0][0] + S11 * V[1][0] + S12 * V[2][0];
    float b0z = S20 * V[0][0] + S21 * V[1][0] + S22 * V[2][0];
    float b1x = S00 * V[0][1] + S01 * V[1][1] + S02 * V[2][1];
    float b1y = S10 * V[0][1] + S11 * V[1][1] + S12 * V[2][1];
    float b1z = S20 * V[0][1] + S21 * V[1][1] + S22 * V[2][1];

    float r0 = frsqrt_fast(b0x * b0x + b0y * b0y + b0z * b0z);
    float u0x = b0x * r0, u0y = b0y * r0, u0z = b0z * r0;
    float r1 = frsqrt_fast(b1x * b1x + b1y * b1y + b1z * b1z);
    float u1x = b1x * r1, u1y = b1y * r1, u1z = b1z * r1;
    float u2x = u0y * u1z - u0z * u1y;
    float u2y = u0z * u1x - u0x * u1z;
    float u2z = u0x * u1y - u0y * u1x;

    // R = V U^T, row-major
    float* o = out + (size_t)(vbase + i) * 9;
    o[0] = V[0][0] * u0x + V[0][1] * u1x + V[0][2] * u2x;
    o[1] = V[0][0] * u0y + V[0][1] * u1y + V[0][2] * u2y;
    o[2] = V[0][0] * u0z + V[0][1] * u1z + V[0][2] * u2z;
    o[3] = V[1][0] * u0x + V[1][1] * u1x + V[1][2] * u2x;
    o[4] = V[1][0] * u0y + V[1][1] * u1y + V[1][2] * u2y;
    o[5] = V[1][0] * u0z + V[1][1] * u1z + V[1][2] * u2z;
    o[6] = V[2][0] * u0x + V[2][1] * u1x + V[2][2] * u2x;
    o[7] = V[2][0] * u0y + V[2][1] * u1y + V[2][2] * u2y;
    o[8] = V[2][0] * u0z + V[2][1] * u1z + V[2][2] * u2z;
}

// ---------------------------------------------------------------------------
// Inputs: xyz1, xyz2, neighborList, numNeighbors, accnumNeighbors,
// weightMatrix, rotations, arapWeight
// ---------------------------------------------------------------------------
extern "C" void kernel_launch(void* const* d_in, const int* in_sizes, int n_in,
                              void* d_out, int out_size) {
    const float* xyz1 = (const float*)d_in[0];
    const float* xyz2 = (const float*)d_in[1];
    const int* nbr = (const int*)d_in[2];
    const int* numN = (const int*)d_in[3];
    const int* accN = (const int*)d_in[4];
    const float* wgt = (const float*)d_in[5];
    float* out = (float*)d_out;

    int n = in_sizes[3];            // N vertices
    int b = in_sizes[0] / (3 * n);  // batches
    int npts = b * n;

    pack_kernel<<<(npts + 255) / 256, 256>>>(xyz1, xyz2, npts);

    dim3 grid((n + 255) / 256, b);
    arap_fused_kernel<<<grid, 256>>>(xyz1, xyz2, nbr, numN, accN, wgt, out, n);
}

// round 15
// speedup vs baseline: 1.0875x; 1.0875x over previous
#include <cuda_runtime.h>
#include <cstddef>

// Problem constants (dataset: B=2, N=50000, D=16)
#define MAXB 2
#define MAXN 50000

// Packed coordinates: g_pack[2t] = {x1,y1,z1,0}, g_pack[2t+1] = {x2,y2,z2,0}.
// 32B-aligned pair -> both float4 gathers for one neighbor hit ONE 32B sector.
__device__ float4 g_pack[2 * MAXB * MAXN];

// Monotonic grid-barrier counter. NEVER reset: each launch's blocks arrive and
// wait for the counter to reach the next multiple of gridDim.x, so every call
// does identical work (deterministic, graph-replay safe). Zero-initialized.
__device__ unsigned g_arrive;

// FMA-pipe inverse sqrt (no MUFU). 2 Newton steps: rel err ~5e-6.
__device__ __forceinline__ float frsqrt_fast(float x) {
    float xh = 0.5f * x;
    float y = __int_as_float(0x5f3759df - (__float_as_int(x) >> 1));
    y = y * (1.5f - xh * y * y);
    y = y * (1.5f - xh * y * y);
    return y;
}

// ---------------------------------------------------------------------------
// Exact Givens Jacobi rotation (FMA-pipe only): zeroes K[p][q].
// ---------------------------------------------------------------------------
template <int p, int q>
__device__ __forceinline__ void jrot(float K[3][3], float V[3][3]) {
    constexpr int r3 = 3 - p - q;
    float apq = K[p][q];
    float ad = K[p][p] - K[q][q];
    float b2 = 2.f * apq;
    float rsq = fmaf(ad, ad, b2 * b2) + 1e-30f;
    float w = frsqrt_fast(rsq);
    float r = rsq * w;  // sqrt(rsq)
    float u = r + fabsf(ad);
    float kk = frsqrt_fast(2.f * r * u);
    float c0 = u * kk;
    float s0 = b2 * kk;
    float c, s;
    if (ad >= 0.f) { c = c0; s = s0; }
    else           { c = fabsf(s0); s = copysignf(c0, b2); }

    float kpp = K[p][p], kqq = K[q][q], kpr = K[p][r3], kqr = K[q][r3];
    float cc = c * c, ss = s * s, cs = c * s;
    K[p][p] = cc * kpp + 2.f * cs * apq + ss * kqq;
    K[q][q] = ss * kpp - 2.f * cs * apq + cc * kqq;
    float npq = cs * (kqq - kpp) + (cc - ss) * apq;
    K[p][q] = npq; K[q][p] = npq;
    float npr = fmaf(c, kpr, s * kqr);
    float nqr = fmaf(-s, kpr, c * kqr);
    K[p][r3] = npr; K[r3][p] = npr;
    K[q][r3] = nqr; K[r3][q] = nqr;

#pragma unroll
    for (int i2 = 0; i2 < 3; i2++) {
        float vp = V[i2][p], vq = V[i2][q];
        V[i2][p] = fmaf(c, vp, s * vq);
        V[i2][q] = fmaf(-s, vp, c * vq);
    }
}

// ---------------------------------------------------------------------------
// Single persistent kernel: phase 1 packs coordinates, a software grid
// barrier (all blocks co-resident: grid=391 <= 148 SMs * 3 CTAs, regs=80,
// smem=0 -> residency guaranteed), then phase 2 gathers + solves.
// The barrier spin is FUEL-BOUNDED: if residency were ever violated the
// kernel exits (bench fails visibly) instead of hanging the container.
// ---------------------------------------------------------------------------
__global__ __launch_bounds__(256, 3) void arap_persistent_kernel(
    const float* __restrict__ xyz1, const float* __restrict__ xyz2,
    const int* __restrict__ nbr, const int* __restrict__ numN,
    const int* __restrict__ accN, const float* __restrict__ wgt,
    float* __restrict__ out, int n, int npts) {
    int t = blockIdx.x * blockDim.x + threadIdx.x;

    // ---------------- Phase 1: pack (R2-measured-cheap shape) ----------------
    if (t < npts) {
        float ax = xyz1[3 * t + 0], ay = xyz1[3 * t + 1], az = xyz1[3 * t + 2];
        float cx = xyz2[3 * t + 0], cy = xyz2[3 * t + 1], cz = xyz2[3 * t + 2];
        g_pack[2 * t + 0] = make_float4(ax, ay, az, 0.f);
        g_pack[2 * t + 1] = make_float4(cx, cy, cz, 0.f);
    }

    // ---------------- Grid barrier (monotonic, launch-reusable) -------------
    __syncthreads();
    if (threadIdx.x == 0) {
        __threadfence();  // make this block's pack stores L2-visible
        unsigned my = atomicAdd(&g_arrive, 1u) + 1u;
        unsigned total = gridDim.x;
        unsigned goal = ((my - 1u) / total + 1u) * total;
        unsigned cur;
        unsigned fuel = 1u << 20;  // hang-proof: ~tens of ms worst case
        do {
            asm volatile("ld.global.acquire.gpu.u32 %0, [%1];"
                         : "=r"(cur) : "l"(&g_arrive));
            if (cur >= goal) break;
            __nanosleep(64);
        } while (--fuel);
    }
    __syncthreads();

    // ---------------- Phase 2: gather + covariance + Procrustes -------------
    if (t >= npts) return;
    // Decompose t -> (batch, vertex). B is tiny; avoid integer div.
    int b = 0, i = t;
    while (i >= n) { i -= n; b++; }
    int vbase = b * n;

    // CSR metadata first so wave-0 index loads overlap the self-point loads.
    int start = accN[i];
    int cnt = numN[i];

    const float4* __restrict__ pk = g_pack;
    float4 p1 = pk[2 * (vbase + i) + 0];
    float4 p2 = pk[2 * (vbase + i) + 1];

    float S00 = 0.f, S01 = 0.f, S02 = 0.f;
    float S10 = 0.f, S11 = 0.f, S12 = 0.f;
    float S20 = 0.f, S21 = 0.f, S22 = 0.f;

    auto accum = [&](float4 q1, float4 q2, float wv) {
        float d1x = p1.x - q1.x, d1y = p1.y - q1.y, d1z = p1.z - q1.z;
        float d2x = p2.x - q2.x, d2y = p2.y - q2.y, d2z = p2.z - q2.z;
        float wx = wv * d1x, wy = wv * d1y, wz = wv * d1z;
        S00 = fmaf(wx, d2x, S00); S01 = fmaf(wx, d2y, S01); S02 = fmaf(wx, d2z, S02);
        S10 = fmaf(wy, d2x, S10); S11 = fmaf(wy, d2y, S11); S12 = fmaf(wy, d2z, S12);
        S20 = fmaf(wz, d2x, S20); S21 = fmaf(wz, d2y, S21); S22 = fmaf(wz, d2z, S22);
    };

    if (cnt == 16 && (start & 3) == 0) {
        const int4* n4 = (const int4*)(nbr + start);
        const float4* w4 = (const float4*)(wgt + start);
#pragma unroll
        for (int wave = 0; wave < 4; wave++) {
            int4 nn = n4[wave];
            float4 ww = w4[wave];
            // Front-batch 8 coordinate gathers (MLP=8, 32 regs in flight).
            float4 a1 = pk[2 * (vbase + nn.x) + 0];
            float4 a2 = pk[2 * (vbase + nn.x) + 1];
            float4 b1 = pk[2 * (vbase + nn.y) + 0];
            float4 b2 = pk[2 * (vbase + nn.y) + 1];
            float4 c1 = pk[2 * (vbase + nn.z) + 0];
            float4 c2 = pk[2 * (vbase + nn.z) + 1];
            float4 d1 = pk[2 * (vbase + nn.w) + 0];
            float4 d2 = pk[2 * (vbase + nn.w) + 1];
            accum(a1, a2, ww.x);
            accum(b1, b2, ww.y);
            accum(c1, c2, ww.z);
            accum(d1, d2, ww.w);
        }
    } else {
        for (int k = 0; k < cnt; k++) {
            int j = nbr[start + k];
            accum(pk[2 * (vbase + j) + 0], pk[2 * (vbase + j) + 1], wgt[start + k]);
        }
    }

    // ---- Procrustes solve ----
    float K[3][3];
    K[0][0] = S00 * S00 + S10 * S10 + S20 * S20;
    K[0][1] = S00 * S01 + S10 * S11 + S20 * S21;
    K[0][2] = S00 * S02 + S10 * S12 + S20 * S22;
    K[1][1] = S01 * S01 + S11 * S11 + S21 * S21;
    K[1][2] = S01 * S02 + S11 * S12 + S21 * S22;
    K[2][2] = S02 * S02 + S12 * S12 + S22 * S22;
    K[1][0] = K[0][1]; K[2][0] = K[0][2]; K[2][1] = K[1][2];

    float V[3][3] = {{1.f, 0.f, 0.f}, {0.f, 1.f, 0.f}, {0.f, 0.f, 1.f}};
#pragma unroll
    for (int sweep = 0; sweep < 4; sweep++) {
        jrot<0, 1>(K, V);
        jrot<1, 2>(K, V);
        jrot<0, 2>(K, V);
    }

    // Sort eigenpairs descending.
    float l0 = K[0][0], l1 = K[1][1], l2 = K[2][2], tt;
    if (l0 < l1) {
        tt = l0; l0 = l1; l1 = tt;
        tt = V[0][0]; V[0][0] = V[0][1]; V[0][1] = tt;
        tt = V[1][0]; V[1][0] = V[1][1]; V[1][1] = tt;
        tt = V[2][0]; V[2][0] = V[2][1]; V[2][1] = tt;
    }
    if (l0 < l2) {
        tt = l0; l0 = l2; l2 = tt;
        tt = V[0][0]; V[0][0] = V[0][2]; V[0][2] = tt;
        tt = V[1][0]; V[1][0] = V[1][2]; V[1][2] = tt;
        tt = V[2][0]; V[2][0] = V[2][2]; V[2][2] = tt;
    }
    if (l1 < l2) {
        tt = l1; l1 = l2; l2 = tt;
        tt = V[0][1]; V[0][1] = V[0][2]; V[0][2] = tt;
        tt = V[1][1]; V[1][1] = V[1][2]; V[1][2] = tt;
        tt = V[2][1]; V[2][1] = V[2][2]; V[2][2] = tt;
    }

    // Force det(V) = +1.
    {
        float cx = V[1][1] * V[2][2] - V[2][1] * V[1][2];
        float cy = V[2][1] * V[0][2] - V[0][1] * V[2][2];
        float cz = V[0][1] * V[1][2] - V[1][1] * V[0][2];
        float det = V[0][0] * cx + V[1][0] * cy + V[2][0] * cz;
        if (det < 0.f) { V[0][2] = -V[0][2]; V[1][2] = -V[1][2]; V[2][2] = -V[2][2]; }
    }

    // u0 = S v0 / |S v0|, u1 = S v1 / |S v1|, u2 = u0 x u1 (det(U)=+1: the
    // reference's reflection fix lands on the smallest singular direction).
    float b0x = S00 * V[0][0] + S01 * V[1][0] + S02 * V[2][0];
    float b0y = S10 * V[0][0] + S11 * V[1][0] + S12 * V[2][0];
    float b0z = S20 * V[0][0] + S21 * V[1][0] + S22 * V[2][0];
    float b1x = S00 * V[0][1] + S01 * V[1][1] + S02 * V[2][1];
    float b1y = S10 * V[0][1] + S11 * V[1][1] + S12 * V[2][1];
    float b1z = S20 * V[0][1] + S21 * V[1][1] + S22 * V[2][1];

    float r0 = frsqrt_fast(b0x * b0x + b0y * b0y + b0z * b0z);
    float u0x = b0x * r0, u0y = b0y * r0, u0z = b0z * r0;
    float r1 = frsqrt_fast(b1x * b1x + b1y * b1y + b1z * b1z);
    float u1x = b1x * r1, u1y = b1y * r1, u1z = b1z * r1;
    float u2x = u0y * u1z - u0z * u1y;
    float u2y = u0z * u1x - u0x * u1z;
    float u2z = u0x * u1y - u0y * u1x;

    // R = V U^T, row-major
    float* o = out + (size_t)(vbase + i) * 9;
    o[0] = V[0][0] * u0x + V[0][1] * u1x + V[0][2] * u2x;
    o[1] = V[0][0] * u0y + V[0][1] * u1y + V[0][2] * u2y;
    o[2] = V[0][0] * u0z + V[0][1] * u1z + V[0][2] * u2z;
    o[3] = V[1][0] * u0x + V[1][1] * u1x + V[1][2] * u2x;
    o[4] = V[1][0] * u0y + V[1][1] * u1y + V[1][2] * u2y;
    o[5] = V[1][0] * u0z + V[1][1] * u1z + V[1][2] * u2z;
    o[6] = V[2][0] * u0x + V[2][1] * u1x + V[2][2] * u2x;
    o[7] = V[2][0] * u0y + V[2][1] * u1y + V[2][2] * u2y;
    o[8] = V[2][0] * u0z + V[2][1] * u1z + V[2][2] * u2z;
}

// ---------------------------------------------------------------------------
// Inputs: xyz1, xyz2, neighborList, numNeighbors, accnumNeighbors,
// weightMatrix, rotations, arapWeight
// ---------------------------------------------------------------------------
extern "C" void kernel_launch(void* const* d_in, const int* in_sizes, int n_in,
                              void* d_out, int out_size) {
    const float* xyz1 = (const float*)d_in[0];
    const float* xyz2 = (const float*)d_in[1];
    const int* nbr = (const int*)d_in[2];
    const int* numN = (const int*)d_in[3];
    const int* accN = (const int*)d_in[4];
    const float* wgt = (const float*)d_in[5];
    float* out = (float*)d_out;

    int n = in_sizes[3];            // N vertices
    int b = in_sizes[0] / (3 * n);  // batches
    int npts = b * n;

    // Single persistent launch: grid must be co-resident for the software
    // barrier. 391 blocks <= 148 SMs * 3 CTAs (enforced by launch bounds).
    int nblk = (npts + 255) / 256;
    arap_persistent_kernel<<<nblk, 256>>>(xyz1, xyz2, nbr, numN, accN, wgt,
                                          out, n, npts);
}

// round 17
// speedup vs baseline: 1.3500x; 1.2414x over previous
#include <cuda_runtime.h>
#include <cstddef>

// Problem constants (dataset: B=2, N=50000, D=16)
#define MAXB 2
#define MAXN 50000

// Batch-merged record, 64B per VERTEX (half a 128B line):
//   g_rec[v*4+0] = batch0 p1   g_rec[v*4+1] = batch0 p2
//   g_rec[v*4+2] = batch1 p1   g_rec[v*4+3] = batch1 p2
// Lane pairs (2k,2k+1) gather the same vertex for the two batches -> their
// requests land in the SAME 128B line -> distinct-line misses per LDG halve.
__device__ float4 g_rec[4 * MAXN];

// FMA-pipe inverse sqrt (no MUFU). 2 Newton steps: rel err ~5e-6.
__device__ __forceinline__ float frsqrt_fast(float x) {
    float xh = 0.5f * x;
    float y = __int_as_float(0x5f3759df - (__float_as_int(x) >> 1));
    y = y * (1.5f - xh * y * y);
    y = y * (1.5f - xh * y * y);
    return y;
}

// ---------------------------------------------------------------------------
// Kernel 1: pack into batch-merged records. Thread t = linear point index
// (coalesced stride-3 reads, same as the measured-cheap R2 pack); stores two
// float4s at v*64 + b*32.
// ---------------------------------------------------------------------------
__global__ void pack_kernel(const float* __restrict__ xyz1,
                            const float* __restrict__ xyz2, int n, int npts) {
    int t = blockIdx.x * blockDim.x + threadIdx.x;
    if (t >= npts) return;
    int b = (t >= n) ? 1 : 0;
    int v = t - (b ? n : 0);
    float ax = xyz1[3 * t + 0], ay = xyz1[3 * t + 1], az = xyz1[3 * t + 2];
    float cx = xyz2[3 * t + 0], cy = xyz2[3 * t + 1], cz = xyz2[3 * t + 2];
    g_rec[v * 4 + b * 2 + 0] = make_float4(ax, ay, az, 0.f);
    g_rec[v * 4 + b * 2 + 1] = make_float4(cx, cy, cz, 0.f);
}

// ---------------------------------------------------------------------------
// Exact Givens Jacobi rotation (FMA-pipe only): zeroes K[p][q].
// ---------------------------------------------------------------------------
template <int p, int q>
__device__ __forceinline__ void jrot(float K[3][3], float V[3][3]) {
    constexpr int r3 = 3 - p - q;
    float apq = K[p][q];
    float ad = K[p][p] - K[q][q];
    float b2 = 2.f * apq;
    float rsq = fmaf(ad, ad, b2 * b2) + 1e-30f;
    float w = frsqrt_fast(rsq);
    float r = rsq * w;  // sqrt(rsq)
    float u = r + fabsf(ad);
    float kk = frsqrt_fast(2.f * r * u);
    float c0 = u * kk;
    float s0 = b2 * kk;
    float c, s;
    if (ad >= 0.f) { c = c0; s = s0; }
    else           { c = fabsf(s0); s = copysignf(c0, b2); }

    float kpp = K[p][p], kqq = K[q][q], kpr = K[p][r3], kqr = K[q][r3];
    float cc = c * c, ss = s * s, cs = c * s;
    K[p][p] = cc * kpp + 2.f * cs * apq + ss * kqq;
    K[q][q] = ss * kpp - 2.f * cs * apq + cc * kqq;
    float npq = cs * (kqq - kpp) + (cc - ss) * apq;
    K[p][q] = npq; K[q][p] = npq;
    float npr = fmaf(c, kpr, s * kqr);
    float nqr = fmaf(-s, kpr, c * kqr);
    K[p][r3] = npr; K[r3][p] = npr;
    K[q][r3] = nqr; K[r3][q] = nqr;

#pragma unroll
    for (int i2 = 0; i2 < 3; i2++) {
        float vp = V[i2][p], vq = V[i2][q];
        V[i2][p] = fmaf(c, vp, s * vq);
        V[i2][q] = fmaf(-s, vp, c * vq);
    }
}

// ---------------------------------------------------------------------------
// Kernel 2: thread t = 2*vertex + batch. Lane pairs share the neighbor list,
// so each gather LDG's lane-pair requests coalesce into one 128B line.
// Body otherwise identical to the best-measured R12 kernel (regs=80, occ 3).
// ---------------------------------------------------------------------------
__global__ __launch_bounds__(256, 3) void arap_fused_kernel(
    const int* __restrict__ nbr, const int* __restrict__ numN,
    const int* __restrict__ accN, const float* __restrict__ wgt,
    float* __restrict__ out, int n) {
    int t = blockIdx.x * blockDim.x + threadIdx.x;
    int i = t >> 1;       // vertex
    int b = t & 1;        // batch
    if (i >= n) return;

    // CSR metadata first (lane pairs load identical addresses -> broadcast).
    int start = accN[i];
    int cnt = numN[i];

    const float4* __restrict__ pk = g_rec;
    int selfbase = i * 4 + b * 2;
    float4 p1 = pk[selfbase + 0];
    float4 p2 = pk[selfbase + 1];

    float S00 = 0.f, S01 = 0.f, S02 = 0.f;
    float S10 = 0.f, S11 = 0.f, S12 = 0.f;
    float S20 = 0.f, S21 = 0.f, S22 = 0.f;

    auto accum = [&](float4 q1, float4 q2, float wv) {
        float d1x = p1.x - q1.x, d1y = p1.y - q1.y, d1z = p1.z - q1.z;
        float d2x = p2.x - q2.x, d2y = p2.y - q2.y, d2z = p2.z - q2.z;
        float wx = wv * d1x, wy = wv * d1y, wz = wv * d1z;
        S00 = fmaf(wx, d2x, S00); S01 = fmaf(wx, d2y, S01); S02 = fmaf(wx, d2z, S02);
        S10 = fmaf(wy, d2x, S10); S11 = fmaf(wy, d2y, S11); S12 = fmaf(wy, d2z, S12);
        S20 = fmaf(wz, d2x, S20); S21 = fmaf(wz, d2y, S21); S22 = fmaf(wz, d2z, S22);
    };

    int boff = b * 2;
    if (cnt == 16 && (start & 3) == 0) {
        const int4* n4 = (const int4*)(nbr + start);
        const float4* w4 = (const float4*)(wgt + start);
#pragma unroll
        for (int wave = 0; wave < 4; wave++) {
            int4 nn = n4[wave];
            float4 ww = w4[wave];
            // Front-batch 8 gathers (MLP=8, 32 regs). Lane pair -> same line.
            float4 a1 = pk[nn.x * 4 + boff + 0];
            float4 a2 = pk[nn.x * 4 + boff + 1];
            float4 b1 = pk[nn.y * 4 + boff + 0];
            float4 b2 = pk[nn.y * 4 + boff + 1];
            float4 c1 = pk[nn.z * 4 + boff + 0];
            float4 c2 = pk[nn.z * 4 + boff + 1];
            float4 d1 = pk[nn.w * 4 + boff + 0];
            float4 d2 = pk[nn.w * 4 + boff + 1];
            accum(a1, a2, ww.x);
            accum(b1, b2, ww.y);
            accum(c1, c2, ww.z);
            accum(d1, d2, ww.w);
        }
    } else {
        for (int k = 0; k < cnt; k++) {
            int j = nbr[start + k];
            accum(pk[j * 4 + boff + 0], pk[j * 4 + boff + 1], wgt[start + k]);
        }
    }

    // ---- Procrustes solve ----
    float K[3][3];
    K[0][0] = S00 * S00 + S10 * S10 + S20 * S20;
    K[0][1] = S00 * S01 + S10 * S11 + S20 * S21;
    K[0][2] = S00 * S02 + S10 * S12 + S20 * S22;
    K[1][1] = S01 * S01 + S11 * S11 + S21 * S21;
    K[1][2] = S01 * S02 + S11 * S12 + S21 * S22;
    K[2][2] = S02 * S02 + S12 * S12 + S22 * S22;
    K[1][0] = K[0][1]; K[2][0] = K[0][2]; K[2][1] = K[1][2];

    float V[3][3] = {{1.f, 0.f, 0.f}, {0.f, 1.f, 0.f}, {0.f, 0.f, 1.f}};
#pragma unroll
    for (int sweep = 0; sweep < 4; sweep++) {
        jrot<0, 1>(K, V);
        jrot<1, 2>(K, V);
        jrot<0, 2>(K, V);
    }

    // Sort eigenpairs descending.
    float l0 = K[0][0], l1 = K[1][1], l2 = K[2][2], tt;
    if (l0 < l1) {
        tt = l0; l0 = l1; l1 = tt;
        tt = V[0][0]; V[0][0] = V[0][1]; V[0][1] = tt;
        tt = V[1][0]; V[1][0] = V[1][1]; V[1][1] = tt;
        tt = V[2][0]; V[2][0] = V[2][1]; V[2][1] = tt;
    }
    if (l0 < l2) {
        tt = l0; l0 = l2; l2 = tt;
        tt = V[0][0]; V[0][0] = V[0][2]; V[0][2] = tt;
        tt = V[1][0]; V[1][0] = V[1][2]; V[1][2] = tt;
        tt = V[2][0]; V[2][0] = V[2][2]; V[2][2] = tt;
    }
    if (l1 < l2) {
        tt = l1; l1 = l2; l2 = tt;
        tt = V[0][1]; V[0][1] = V[0][2]; V[0][2] = tt;
        tt = V[1][1]; V[1][1] = V[1][2]; V[1][2] = tt;
        tt = V[2][1]; V[2][1] = V[2][2]; V[2][2] = tt;
    }

    // Force det(V) = +1.
    {
        float cx = V[1][1] * V[2][2] - V[2][1] * V[1][2];
        float cy = V[2][1] * V[0][2] - V[0][1] * V[2][2];
        float cz = V[0][1] * V[1][2] - V[1][1] * V[0][2];
        float det = V[0][0] * cx + V[1][0] * cy + V[2][0] * cz;
        if (det < 0.f) { V[0][2] = -V[0][2]; V[1][2] = -V[1][2]; V[2][2] = -V[2][2]; }
    }

    // u0 = S v0 / |S v0|, u1 = S v1 / |S v1|, u2 = u0 x u1 (det(U)=+1: the
    // reference's reflection fix lands on the smallest singular direction).
    float b0x = S00 * V[0][0] + S01 * V[1][0] + S02 * V[2][0];
    float b0y = S10 * V[0][0] + S11 * V[1][0] + S12 * V[2][0];
    float b0z = S20 * V[0][0] + S21 * V[1][0] + S22 * V[2][0];
    float b1x = S00 * V[0][1] + S01 * V[1][1] + S02 * V[2][1];
    float b1y = S10 * V[0][1] + S11 * V[1][1] + S12 * V[2][1];
    float b1z = S20 * V[0][1] + S21 * V[1][1] + S22 * V[2][1];

    float r0 = frsqrt_fast(b0x * b0x + b0y * b0y + b0z * b0z);
    float u0x = b0x * r0, u0y = b0y * r0, u0z = b0z * r0;
    float r1 = frsqrt_fast(b1x * b1x + b1y * b1y + b1z * b1z);
    float u1x = b1x * r1, u1y = b1y * r1, u1z = b1z * r1;
    float u2x = u0y * u1z - u0z * u1y;
    float u2y = u0z * u1x - u0x * u1z;
    float u2z = u0x * u1y - u0y * u1x;

    // R = V U^T, row-major
    float* o = out + (size_t)(b * n + i) * 9;
    o[0] = V[0][0] * u0x + V[0][1] * u1x + V[0][2] * u2x;
    o[1] = V[0][0] * u0y + V[0][1] * u1y + V[0][2] * u2y;
    o[2] = V[0][0] * u0z + V[0][1] * u1z + V[0][2] * u2z;
    o[3] = V[1][0] * u0x + V[1][1] * u1x + V[1][2] * u2x;
    o[4] = V[1][0] * u0y + V[1][1] * u1y + V[1][2] * u2y;
    o[5] = V[1][0] * u0z + V[1][1] * u1z + V[1][2] * u2z;
    o[6] = V[2][0] * u0x + V[2][1] * u1x + V[2][2] * u2x;
    o[7] = V[2][0] * u0y + V[2][1] * u1y + V[2][2] * u2y;
    o[8] = V[2][0] * u0z + V[2][1] * u1z + V[2][2] * u2z;
}

// ---------------------------------------------------------------------------
// Inputs: xyz1, xyz2, neighborList, numNeighbors, accnumNeighbors,
// weightMatrix, rotations, arapWeight
// ---------------------------------------------------------------------------
extern "C" void kernel_launch(void* const* d_in, const int* in_sizes, int n_in,
                              void* d_out, int out_size) {
    const float* xyz1 = (const float*)d_in[0];
    const float* xyz2 = (const float*)d_in[1];
    const int* nbr = (const int*)d_in[2];
    const int* numN = (const int*)d_in[3];
    const int* accN = (const int*)d_in[4];
    const float* wgt = (const float*)d_in[5];
    float* out = (float*)d_out;

    int n = in_sizes[3];            // N vertices
    int b = in_sizes[0] / (3 * n);  // batches
    int npts = b * n;

    pack_kernel<<<(npts + 255) / 256, 256>>>(xyz1, xyz2, n, npts);

    int nthreads = n * 2;           // 2*vertex + batch lane pairing
    arap_fused_kernel<<<(nthreads + 255) / 256, 256>>>(nbr, numN, accN, wgt,
                                                       out, n);
}